// round 5
// baseline (speedup 1.0000x reference)
#include <cuda_runtime.h>
#include <math.h>

// Problem constants
#define B_    512
#define U_    256
#define T_    256
#define NCW   2048   // 8*U

// Decomposition: 8 batch-groups x 16 unit-blocks = 128 persistent CTAs.
// Dependency is ONLY within a batch-group (16 blocks) -> group-local barriers.
#define NBLK     128
#define NGRP_SZ  16
#define NTHREADS 256
#define BM       64     // batch rows per block
#define BUU      16     // units per block
#define NCOL     128    // 8 gates * 16 units

// Padded smem leading dims
#define WS_LD 132       // W tile  [256][132]
#define HS_LD 260       // h tile  [64][260]
#define MS_LD 144       // m stage [64][144]

#define WS_FLOATS (U_ * WS_LD)    // 33792
#define HS_FLOATS (BM * HS_LD)    // 16640
#define SMEM_BYTES ((WS_FLOATS + HS_FLOATS) * 4)   // 201728 bytes

// h ping-pong buffers (c never leaves registers)
__device__ float g_hA[B_ * U_];
__device__ float g_hB[B_ * U_];
// per-group monotonic barrier counters, one 128B line each (replay-safe)
__device__ unsigned g_arrive[8 * 32];

// ---- packed f32x2 helpers -------------------------------------------------
__device__ __forceinline__ unsigned long long pack2(float a) {
    unsigned long long r;
    asm("mov.b64 %0, {%1, %1};" : "=l"(r) : "f"(a));
    return r;
}
__device__ __forceinline__ void fma2(unsigned long long& d,
                                     unsigned long long a,
                                     unsigned long long b) {
    asm("fma.rn.f32x2 %0, %1, %2, %0;" : "+l"(d) : "l"(a), "l"(b));
}

// ---- fast activations (MUFU.EX2-based) ------------------------------------
__device__ __forceinline__ float sigf(float v) {
    return __fdividef(1.0f, 1.0f + __expf(-v));
}
__device__ __forceinline__ float tanhf_fast(float v) {
    return fmaf(2.0f, sigf(2.0f * v), -1.0f);
}

// ---- group barrier: syncs the 16 CTAs of one batch-group -------------------
__device__ __forceinline__ void group_barrier(int tid, int grp) {
    __syncthreads();
    if (tid == 0) {
        __threadfence();                          // publish h stores (GPU scope)
        unsigned* ctr = &g_arrive[grp * 32];
        unsigned ticket = atomicAdd(ctr, 1u);
        unsigned target = (ticket & ~(NGRP_SZ - 1u)) + NGRP_SZ;
        volatile unsigned* p = ctr;
        while ((int)(*p - target) < 0) { }        // tight spin; L2 RTT paced
        __threadfence();
    }
    __syncthreads();
}

extern __shared__ float smem[];

__global__ __launch_bounds__(NTHREADS, 1)
void nas_persistent(float* __restrict__ out,
                    const float* __restrict__ W,
                    const float* __restrict__ kern,
                    const float* __restrict__ x)
{
    float* ws = smem;                 // [U_][WS_LD]
    float* hs = smem + WS_FLOATS;     // [BM][HS_LD]; aliased by ms [BM][MS_LD]
    __shared__ float ksh[NCOL];
    __shared__ float xs[BM];

    const int tid = threadIdx.x;
    const int bx  = blockIdx.x & 7;    // batch group
    const int by  = blockIdx.x >> 3;   // unit block
    const int b0  = bx * BM;
    const int u0  = by * BUU;

    // ---- Prologue: W slice (256 x 128 cols) -> smem, once for all steps ----
    #pragma unroll
    for (int it = 0; it < 32; it++) {
        int f4 = it * NTHREADS + tid;  // 8192 float4 total
        int k  = f4 >> 5;
        int cg = f4 & 31;
        int g  = cg >> 2;
        int q  = cg & 3;
        const float4 v = *reinterpret_cast<const float4*>(
            &W[(size_t)k * NCW + g * U_ + u0 + q * 4]);
        *reinterpret_cast<float4*>(&ws[k * WS_LD + cg * 4]) = v;
    }
    if (tid < NCOL) {
        ksh[tid] = kern[(tid >> 4) * U_ + u0 + (tid & 15)];
    }

    float creg[4] = {0.0f, 0.0f, 0.0f, 0.0f};   // cell state, register-resident

    const int col_t = tid & 15;   // 16 col-groups of 8 GEMM columns
    const int row_t = tid >> 4;   // 16 row-groups of 4 batch rows

    for (int t = 0; t < T_; t++) {
        const float* hin  = (t & 1) ? g_hB : g_hA;
        float*       hout = (t == T_ - 1) ? out : ((t & 1) ? g_hA : g_hB);

        if (tid < BM) xs[tid] = x[(b0 + tid) * U_ + t];

        unsigned long long acc[4][4];
        #pragma unroll
        for (int i = 0; i < 4; i++)
            #pragma unroll
            for (int j = 0; j < 4; j++)
                acc[i][j] = 0ULL;

        if (t > 0) {
            // Load h tile (64 x 256) with L1 bypass (cross-SM producers)
            #pragma unroll
            for (int it = 0; it < 16; it++) {
                int f4  = it * NTHREADS + tid;   // 4096 float4
                int row = f4 >> 6;
                int q   = f4 & 63;
                const float4 v = __ldcg(reinterpret_cast<const float4*>(
                    &hin[(b0 + row) * U_ + q * 4]));
                *reinterpret_cast<float4*>(&hs[row * HS_LD + q * 4]) = v;
            }
            __syncthreads();

            // GEMM: m[64x128] += h[64x256] @ Wsmem[256x128], packed f32x2.
            #pragma unroll 2
            for (int kk = 0; kk < U_; kk += 4) {
                float4 a4[4];
                #pragma unroll
                for (int i = 0; i < 4; i++)
                    a4[i] = *reinterpret_cast<const float4*>(
                        &hs[(row_t * 4 + i) * HS_LD + kk]);
                #pragma unroll
                for (int dk = 0; dk < 4; dk++) {
                    const float* wrow = &ws[(kk + dk) * WS_LD + col_t * 8];
                    ulonglong2 b01 = *reinterpret_cast<const ulonglong2*>(wrow);
                    ulonglong2 b23 = *reinterpret_cast<const ulonglong2*>(wrow + 4);
                    #pragma unroll
                    for (int i = 0; i < 4; i++) {
                        float av = (dk == 0) ? a4[i].x :
                                   (dk == 1) ? a4[i].y :
                                   (dk == 2) ? a4[i].z : a4[i].w;
                        unsigned long long a2 = pack2(av);
                        fma2(acc[i][0], a2, b01.x);
                        fma2(acc[i][1], a2, b01.y);
                        fma2(acc[i][2], a2, b23.x);
                        fma2(acc[i][3], a2, b23.y);
                    }
                }
            }
            __syncthreads();   // all warps done reading hs before it becomes ms
        }

        // ---- Stage m tile (aliases hs) so each thread gathers its 8 gates --
        float* ms = hs;
        #pragma unroll
        for (int i = 0; i < 4; i++) {
            int row = row_t * 4 + i;
            #pragma unroll
            for (int j = 0; j < 4; j++)
                *reinterpret_cast<unsigned long long*>(
                    &ms[row * MS_LD + col_t * 8 + j * 2]) = acc[i][j];
        }
        __syncthreads();

        // ---- NASCell epilogue: 1024 elements, 4 per thread ----------------
        #pragma unroll
        for (int it = 0; it < 4; it++) {
            int e   = it * NTHREADS + tid;
            int uu  = e & 15;
            int row = e >> 4;
            float xv = xs[row];

            float m[8], iv[8];
            #pragma unroll
            for (int g = 0; g < 8; g++) {
                m[g]  = ms[row * MS_LD + g * 16 + uu];
                iv[g] = xv * ksh[g * 16 + uu];
            }

            float l10 = sigf(iv[0] + m[0]);
            float l11 = fmaxf(iv[1] + m[1], 0.0f);
            float l12 = sigf(iv[2] + m[2]);
            float l13 = fmaxf(iv[3] * m[3], 0.0f);
            float l14 = tanhf_fast(iv[4] + m[4]);
            float l15 = sigf(iv[5] + m[5]);
            float l16 = tanhf_fast(iv[6] + m[6]);
            float l17 = sigf(iv[7] + m[7]);

            float l20 = tanhf_fast(l10 * l11);
            float l21 = tanhf_fast(l12 + l13);
            float l22 = tanhf_fast(l14 * l15);
            float l23 = sigf(l16 + l17);

            l20 = tanhf_fast(l20 + creg[it]);
            float nc  = l20 * l21;
            float l31 = tanhf_fast(l22 + l23);
            float nh  = tanhf_fast(nc * l31);

            creg[it] = nc;
            hout[(b0 + row) * U_ + u0 + uu] = nh;
        }

        if (t != T_ - 1) group_barrier(tid, bx);
    }
}

extern "C" void kernel_launch(void* const* d_in, const int* in_sizes, int n_in,
                              void* d_out, int out_size) {
    const float* x    = nullptr;
    const float* kern = nullptr;
    const float* W    = nullptr;
    for (int i = 0; i < n_in; i++) {
        if (in_sizes[i] == B_ * U_)       x    = (const float*)d_in[i];
        else if (in_sizes[i] == 8 * U_)   kern = (const float*)d_in[i];
        else if (in_sizes[i] == U_ * NCW) W    = (const float*)d_in[i];
    }
    float* out = (float*)d_out;

    cudaFuncSetAttribute(nas_persistent,
                         cudaFuncAttributeMaxDynamicSharedMemorySize, SMEM_BYTES);
    nas_persistent<<<NBLK, NTHREADS, SMEM_BYTES>>>(out, W, kern, x);
}

// round 7
// speedup vs baseline: 2.4008x; 2.4008x over previous
#include <cuda_runtime.h>
#include <cstdint>

// Problem constants
#define B_    512
#define U_    256
#define T_    256
#define NCW   2048   // 8*U

// Decomposition: 4 batch-groups (128 rows) x 32 unit-blocks (8 units) = 128 CTAs
#define NBLK     128
#define NTHREADS 256    // 8 warps; warp w owns rows w*16..w*16+15, all 64 cols
#define BM       128
#define GRP      32     // CTAs per batch group

// Padded smem rows: 264 bf16 = 132 words = 528 B  (132 % 32 == 4 -> LDS conflict-free)
#define LDW   132
#define A_HI  0
#define A_MID 67584      // 128*528
#define B_HI  135168
#define B_MID 168960     // + 64*528
#define SMEM_TOTAL 202752

// h ping-pong buffers (c never leaves registers)
__device__ float g_hA[B_ * U_];
__device__ float g_hB[B_ * U_];
// per-group monotonic barrier counters (one 128B line each; replay-safe)
__device__ unsigned g_arrive[4 * 32];

// ---- helpers ---------------------------------------------------------------
// pack {hi_elem, lo_elem} -> b32 (lo = lower k index)
__device__ __forceinline__ uint32_t bfpack(float hi, float lo) {
    uint32_t r;
    asm("cvt.rn.bf16x2.f32 %0, %1, %2;" : "=r"(r) : "f"(hi), "f"(lo));
    return r;
}
__device__ __forceinline__ float sigf(float v) {
    return __fdividef(1.0f, 1.0f + __expf(-v));
}
__device__ __forceinline__ float tanhf_fast(float v) {
    return fmaf(2.0f, sigf(2.0f * v), -1.0f);
}
__device__ __forceinline__ void mma16816(float* c, const uint32_t* a,
                                         uint32_t b0, uint32_t b1) {
    asm volatile(
        "mma.sync.aligned.m16n8k16.row.col.f32.bf16.bf16.f32 "
        "{%0,%1,%2,%3},{%4,%5,%6,%7},{%8,%9},{%0,%1,%2,%3};"
        : "+f"(c[0]), "+f"(c[1]), "+f"(c[2]), "+f"(c[3])
        : "r"(a[0]), "r"(a[1]), "r"(a[2]), "r"(a[3]), "r"(b0), "r"(b1));
}

// ---- group barrier (32 CTAs of one batch group) ----------------------------
__device__ __forceinline__ void group_barrier(int tid, int grp) {
    __syncthreads();
    if (tid == 0) {
        __threadfence();
        unsigned* ctr = &g_arrive[grp * 32];
        unsigned ticket = atomicAdd(ctr, 1u);
        unsigned target = (ticket & ~(GRP - 1u)) + GRP;
        volatile unsigned* p = ctr;
        while ((int)(*p - target) < 0) { }
        __threadfence();
    }
    __syncthreads();
}

extern __shared__ char smem[];

__global__ __launch_bounds__(NTHREADS, 1)
void nas_hmma(float* __restrict__ out,
              const float* __restrict__ W,
              const float* __restrict__ kern,
              const float* __restrict__ x)
{
    uint32_t* Ah = reinterpret_cast<uint32_t*>(smem + A_HI);   // [128][LDW]
    uint32_t* Am = reinterpret_cast<uint32_t*>(smem + A_MID);
    uint32_t* Bh = reinterpret_cast<uint32_t*>(smem + B_HI);   // [64][LDW]
    uint32_t* Bm = reinterpret_cast<uint32_t*>(smem + B_MID);

    const int tid  = threadIdx.x;
    const int wid  = tid >> 5;
    const int lane = tid & 31;
    const int quad = lane >> 2;     // 0..7
    const int ql   = lane & 3;      // 0..3
    const int bx   = blockIdx.x & 3;    // batch group (128 rows)
    const int by   = blockIdx.x >> 2;   // unit block (8 units)
    const int b0   = bx * BM;
    const int u0   = by * 8;

    const int r0 = wid * 16 + quad;     // thread's two rows within the CTA tile
    const int r1 = r0 + 8;
    const int uu0 = ql * 2;             // thread's two units

    // ---- Prologue: W slice -> bf16 hi/mid tiles. B[n][k] = W[k][gcol],
    // n = g*8 + uu, gcol = g*256 + u0 + uu. 64 n x 128 k-pairs = 8192 items.
    for (int i = 0; i < 32; i++) {
        int p  = tid + i * NTHREADS;
        int n  = p >> 7;
        int kp = (p & 127) * 2;
        int gcol = (n >> 3) * U_ + u0 + (n & 7);
        float w0 = W[(size_t)kp * NCW + gcol];
        float w1 = W[(size_t)(kp + 1) * NCW + gcol];
        uint32_t hp = bfpack(w1, w0);
        float f0 = __uint_as_float(hp << 16);
        float f1 = __uint_as_float(hp & 0xFFFF0000u);
        uint32_t mp = bfpack(w1 - f1, w0 - f0);
        Bh[n * LDW + (kp >> 1)] = hp;
        Bm[n * LDW + (kp >> 1)] = mp;
    }
    // kernel row -> registers (fixed for all steps): kr[g][us]
    float kr[16];
    #pragma unroll
    for (int g = 0; g < 8; g++) {
        kr[g * 2 + 0] = __ldg(&kern[g * U_ + u0 + uu0 + 0]);
        kr[g * 2 + 1] = __ldg(&kern[g * U_ + u0 + uu0 + 1]);
    }

    float creg[4] = {0.0f, 0.0f, 0.0f, 0.0f};   // c[(rs,us)], register-resident
    __syncthreads();

    for (int t = 0; t < T_; t++) {
        const float* hin  = (t & 1) ? g_hB : g_hA;
        float*       hout = (t == T_ - 1) ? out : ((t & 1) ? g_hA : g_hB);

        float acc[8][4];
        #pragma unroll
        for (int g = 0; g < 8; g++)
            #pragma unroll
            for (int j = 0; j < 4; j++)
                acc[g][j] = 0.0f;

        if (t > 0) {
            // ---- h -> bf16 hi/mid A tiles: 128 rows x 32 chunks(8 floats) ----
            #pragma unroll 4
            for (int i = 0; i < 16; i++) {
                int idx = tid + i * NTHREADS;     // 0..4095
                int row = idx >> 5;
                int c8  = idx & 31;
                const float4* src = reinterpret_cast<const float4*>(
                    &hin[(b0 + row) * U_ + c8 * 8]);
                float4 v0 = __ldcg(src);
                float4 v1 = __ldcg(src + 1);
                uint32_t h0 = bfpack(v0.y, v0.x);
                uint32_t h1 = bfpack(v0.w, v0.z);
                uint32_t h2 = bfpack(v1.y, v1.x);
                uint32_t h3 = bfpack(v1.w, v1.z);
                uint32_t m0 = bfpack(v0.y - __uint_as_float(h0 & 0xFFFF0000u),
                                     v0.x - __uint_as_float(h0 << 16));
                uint32_t m1 = bfpack(v0.w - __uint_as_float(h1 & 0xFFFF0000u),
                                     v0.z - __uint_as_float(h1 << 16));
                uint32_t m2 = bfpack(v1.y - __uint_as_float(h2 & 0xFFFF0000u),
                                     v1.x - __uint_as_float(h2 << 16));
                uint32_t m3 = bfpack(v1.w - __uint_as_float(h3 & 0xFFFF0000u),
                                     v1.z - __uint_as_float(h3 << 16));
                uint32_t wofs = row * LDW + c8 * 4;
                *reinterpret_cast<uint4*>(&Ah[wofs]) = make_uint4(h0, h1, h2, h3);
                *reinterpret_cast<uint4*>(&Am[wofs]) = make_uint4(m0, m1, m2, m3);
            }
            __syncthreads();

            // ---- HMMA GEMM: 3-pass bf16 split, K=256 (16 k-steps) ----------
            #pragma unroll 1
            for (int ks = 0; ks < 16; ks++) {
                const int kw = ks * 8;            // word offset of k0 = ks*16
                uint32_t ah[4], am[4];
                ah[0] = Ah[r0 * LDW + kw + ql];
                ah[1] = Ah[r1 * LDW + kw + ql];
                ah[2] = Ah[r0 * LDW + kw + 4 + ql];
                ah[3] = Ah[r1 * LDW + kw + 4 + ql];
                am[0] = Am[r0 * LDW + kw + ql];
                am[1] = Am[r1 * LDW + kw + ql];
                am[2] = Am[r0 * LDW + kw + 4 + ql];
                am[3] = Am[r1 * LDW + kw + 4 + ql];
                #pragma unroll
                for (int g = 0; g < 8; g++) {
                    int nb = (g * 8 + quad) * LDW + kw + ql;
                    uint32_t bh0 = Bh[nb], bh1 = Bh[nb + 4];
                    uint32_t bm0 = Bm[nb], bm1 = Bm[nb + 4];
                    mma16816(acc[g], ah, bh0, bh1);
                    mma16816(acc[g], ah, bm0, bm1);
                    mma16816(acc[g], am, bh0, bh1);
                }
            }
        }

        // ---- In-register NASCell epilogue: 2 rows x 2 units per thread -----
        #pragma unroll
        for (int rs = 0; rs < 2; rs++) {
            int row = rs ? r1 : r0;
            float xv = __ldg(&x[(b0 + row) * U_ + t]);
            float nh2[2];
            #pragma unroll
            for (int us = 0; us < 2; us++) {
                int ci = rs * 2 + us;
                float l10, l11, l12, l13, l14, l15, l16, l17;
                {
                    float i0 = xv * kr[0 * 2 + us], m0 = acc[0][ci];
                    float i1 = xv * kr[1 * 2 + us], m1 = acc[1][ci];
                    float i2 = xv * kr[2 * 2 + us], m2 = acc[2][ci];
                    float i3 = xv * kr[3 * 2 + us], m3 = acc[3][ci];
                    float i4 = xv * kr[4 * 2 + us], m4 = acc[4][ci];
                    float i5 = xv * kr[5 * 2 + us], m5 = acc[5][ci];
                    float i6 = xv * kr[6 * 2 + us], m6 = acc[6][ci];
                    float i7 = xv * kr[7 * 2 + us], m7 = acc[7][ci];
                    l10 = sigf(i0 + m0);
                    l11 = fmaxf(i1 + m1, 0.0f);
                    l12 = sigf(i2 + m2);
                    l13 = fmaxf(i3 * m3, 0.0f);
                    l14 = tanhf_fast(i4 + m4);
                    l15 = sigf(i5 + m5);
                    l16 = tanhf_fast(i6 + m6);
                    l17 = sigf(i7 + m7);
                }
                float l20 = tanhf_fast(l10 * l11);
                float l21 = tanhf_fast(l12 + l13);
                float l22 = tanhf_fast(l14 * l15);
                float l23 = sigf(l16 + l17);

                l20 = tanhf_fast(l20 + creg[ci]);
                float nc  = l20 * l21;
                float l31 = tanhf_fast(l22 + l23);
                float nh  = tanhf_fast(nc * l31);

                creg[ci] = nc;
                nh2[us]  = nh;
            }
            *reinterpret_cast<float2*>(&hout[(b0 + row) * U_ + u0 + uu0]) =
                make_float2(nh2[0], nh2[1]);
        }

        if (t != T_ - 1) group_barrier(tid, bx);
    }
}

extern "C" void kernel_launch(void* const* d_in, const int* in_sizes, int n_in,
                              void* d_out, int out_size) {
    const float* x    = nullptr;
    const float* kern = nullptr;
    const float* W    = nullptr;
    for (int i = 0; i < n_in; i++) {
        if (in_sizes[i] == B_ * U_)       x    = (const float*)d_in[i];
        else if (in_sizes[i] == 8 * U_)   kern = (const float*)d_in[i];
        else if (in_sizes[i] == U_ * NCW) W    = (const float*)d_in[i];
    }
    float* out = (float*)d_out;

    cudaFuncSetAttribute(nas_hmma, cudaFuncAttributeMaxDynamicSharedMemorySize,
                         SMEM_TOTAL);
    nas_hmma<<<NBLK, NTHREADS, SMEM_TOTAL>>>(out, W, kern, x);
}

// round 8
// speedup vs baseline: 3.2444x; 1.3514x over previous
#include <cuda_runtime.h>
#include <cstdint>

// Problem constants
#define B_    512
#define U_    256
#define T_    256
#define NCW   2048   // 8*U

// Decomposition: 4 batch-groups (128 rows) x 32 unit-blocks (8 units) = 128 CTAs
#define NBLK     128
#define NTHREADS 256    // 8 warps; warp w owns rows w*16..w*16+15, all 64 cols
#define BM       128
#define GRP      32     // CTAs per batch group

// fp16 tiles, row pitch 264 fp16 = 528 B (132 words; 132 % 32 == 4 -> ldmatrix
// row addresses land on distinct 16B bank-groups => conflict-free)
#define LDH   264
#define LDWRD 132
#define A_OFF 0
#define B_OFF 67584               // 128*528
#define SMEM_TOTAL 101376         // + 64*528

// h ping-pong buffers (c never leaves registers)
__device__ float g_hA[B_ * U_];
__device__ float g_hB[B_ * U_];
// per-group monotonic barrier counters (one 128B line each; replay-safe)
__device__ unsigned g_arrive[4 * 32];

// ---- helpers ---------------------------------------------------------------
__device__ __forceinline__ uint32_t smem_u32(const void* p) {
    uint32_t a;
    asm("{ .reg .u64 t; cvta.to.shared.u64 t, %1; cvt.u32.u64 %0, t; }"
        : "=r"(a) : "l"(p));
    return a;
}
// pack {hi_elem, lo_elem} -> f16x2 (lo = lower k index / lower address)
__device__ __forceinline__ uint32_t hfpack(float hi, float lo) {
    uint32_t r;
    asm("cvt.rn.f16x2.f32 %0, %1, %2;" : "=r"(r) : "f"(hi), "f"(lo));
    return r;
}
__device__ __forceinline__ float sigf(float v) {
    return __fdividef(1.0f, 1.0f + __expf(-v));
}
__device__ __forceinline__ float tanhf_fast(float v) {
    return fmaf(2.0f, sigf(2.0f * v), -1.0f);
}
__device__ __forceinline__ void ldsm4(uint32_t* r, uint32_t addr) {
    asm volatile("ldmatrix.sync.aligned.m8n8.x4.shared.b16 {%0,%1,%2,%3}, [%4];"
                 : "=r"(r[0]), "=r"(r[1]), "=r"(r[2]), "=r"(r[3]) : "r"(addr));
}
__device__ __forceinline__ void mma16816(float* c, const uint32_t* a,
                                         uint32_t b0, uint32_t b1) {
    asm volatile(
        "mma.sync.aligned.m16n8k16.row.col.f32.f16.f16.f32 "
        "{%0,%1,%2,%3},{%4,%5,%6,%7},{%8,%9},{%0,%1,%2,%3};"
        : "+f"(c[0]), "+f"(c[1]), "+f"(c[2]), "+f"(c[3])
        : "r"(a[0]), "r"(a[1]), "r"(a[2]), "r"(a[3]), "r"(b0), "r"(b1));
}

// ---- group barrier (32 CTAs of one batch group) ----------------------------
__device__ __forceinline__ void group_barrier(int tid, int grp) {
    __syncthreads();
    if (tid == 0) {
        __threadfence();
        unsigned* ctr = &g_arrive[grp * 32];
        unsigned ticket = atomicAdd(ctr, 1u);
        unsigned target = (ticket & ~(GRP - 1u)) + GRP;
        volatile unsigned* p = ctr;
        while ((int)(*p - target) < 0) { }
        __threadfence();
    }
    __syncthreads();
}

extern __shared__ char smem[];

__global__ __launch_bounds__(NTHREADS, 1)
void nas_hmma(float* __restrict__ out,
              const float* __restrict__ W,
              const float* __restrict__ kern,
              const float* __restrict__ x)
{
    uint32_t* Aw = reinterpret_cast<uint32_t*>(smem + A_OFF);  // [128][LDWRD]
    uint32_t* Bw = reinterpret_cast<uint32_t*>(smem + B_OFF);  // [64][LDWRD]

    const int tid  = threadIdx.x;
    const int wid  = tid >> 5;
    const int lane = tid & 31;
    const int quad = lane >> 2;     // 0..7
    const int ql   = lane & 3;      // 0..3
    const int bx   = blockIdx.x & 3;    // batch group (128 rows)
    const int by   = blockIdx.x >> 2;   // unit block (8 units)
    const int b0   = bx * BM;
    const int u0   = by * 8;

    const int r0  = wid * 16 + quad;    // thread's two rows within the CTA tile
    const int r1  = r0 + 8;
    const int uu0 = ql * 2;             // thread's two units

    // ---- Prologue: W slice -> fp16 tile. B[n][k] = W[k][gcol],
    // n = g*8 + uu, gcol = (n>>3)*256 + u0 + (n&7). 64 n x 128 k-pairs.
    for (int i = 0; i < 32; i++) {
        int p  = tid + i * NTHREADS;
        int n  = p >> 7;
        int kp = (p & 127) * 2;
        int gcol = (n >> 3) * U_ + u0 + (n & 7);
        float w0 = W[(size_t)kp * NCW + gcol];
        float w1 = W[(size_t)(kp + 1) * NCW + gcol];
        Bw[n * LDWRD + (kp >> 1)] = hfpack(w1, w0);
    }
    // kernel row -> registers (fixed for all steps): kr[g][us]
    float kr[16];
    #pragma unroll
    for (int g = 0; g < 8; g++) {
        kr[g * 2 + 0] = __ldg(&kern[g * U_ + u0 + uu0 + 0]);
        kr[g * 2 + 1] = __ldg(&kern[g * U_ + u0 + uu0 + 1]);
    }

    // ldmatrix base addresses (byte offsets advance 32B per 16-k step)
    const uint32_t sA = smem_u32(smem) + A_OFF;
    const uint32_t sB = smem_u32(smem) + B_OFF;
    const int rowA  = wid * 16 + ((lane >> 3) & 1) * 8 + (lane & 7);
    const uint32_t aBase = sA + rowA * (LDH * 2) + (lane >> 4) * 16;
    uint32_t bBase[4];
    #pragma unroll
    for (int gi = 0; gi < 4; gi++) {
        int g  = gi * 2 + (lane >> 4);
        int nB = g * 8 + (lane & 7);
        bBase[gi] = sB + nB * (LDH * 2) + ((lane >> 3) & 1) * 16;
    }

    float creg[4] = {0.0f, 0.0f, 0.0f, 0.0f};   // c[(rs,us)], register-resident
    __syncthreads();

    for (int t = 0; t < T_; t++) {
        const float* hin  = (t & 1) ? g_hB : g_hA;
        float*       hout = (t == T_ - 1) ? out : ((t & 1) ? g_hA : g_hB);

        float acc[8][4];
        #pragma unroll
        for (int g = 0; g < 8; g++)
            #pragma unroll
            for (int j = 0; j < 4; j++)
                acc[g][j] = 0.0f;

        if (t > 0) {
            // ---- h -> fp16 A tile: 128 rows x 32 chunks(8 floats) ----------
            #pragma unroll 4
            for (int i = 0; i < 16; i++) {
                int idx = tid + i * NTHREADS;     // 0..4095
                int row = idx >> 5;
                int c8  = idx & 31;
                const float4* src = reinterpret_cast<const float4*>(
                    &hin[(b0 + row) * U_ + c8 * 8]);
                float4 v0 = __ldcg(src);
                float4 v1 = __ldcg(src + 1);
                uint32_t p0 = hfpack(v0.y, v0.x);
                uint32_t p1 = hfpack(v0.w, v0.z);
                uint32_t p2 = hfpack(v1.y, v1.x);
                uint32_t p3 = hfpack(v1.w, v1.z);
                *reinterpret_cast<uint4*>(&Aw[row * LDWRD + c8 * 4]) =
                    make_uint4(p0, p1, p2, p3);
            }
            __syncthreads();

            // ---- HMMA GEMM: single-pass fp16, K=256 (16 k-steps) -----------
            #pragma unroll
            for (int ks = 0; ks < 16; ks++) {
                uint32_t a[4];
                ldsm4(a, aBase + ks * 32);
                #pragma unroll
                for (int gi = 0; gi < 4; gi++) {
                    uint32_t b[4];
                    ldsm4(b, bBase[gi] + ks * 32);
                    mma16816(acc[gi * 2 + 0], a, b[0], b[1]);
                    mma16816(acc[gi * 2 + 1], a, b[2], b[3]);
                }
            }
            __syncthreads();   // A tile free for next step's convert
        }

        // ---- In-register NASCell epilogue: 2 rows x 2 units per thread -----
        #pragma unroll
        for (int rs = 0; rs < 2; rs++) {
            int row = rs ? r1 : r0;
            float xv = __ldg(&x[(b0 + row) * U_ + t]);
            float nh2[2];
            #pragma unroll
            for (int us = 0; us < 2; us++) {
                int ci = rs * 2 + us;
                float i0 = xv * kr[0 * 2 + us], m0 = acc[0][ci];
                float i1 = xv * kr[1 * 2 + us], m1 = acc[1][ci];
                float i2 = xv * kr[2 * 2 + us], m2 = acc[2][ci];
                float i3 = xv * kr[3 * 2 + us], m3 = acc[3][ci];
                float i4 = xv * kr[4 * 2 + us], m4 = acc[4][ci];
                float i5 = xv * kr[5 * 2 + us], m5 = acc[5][ci];
                float i6 = xv * kr[6 * 2 + us], m6 = acc[6][ci];
                float i7 = xv * kr[7 * 2 + us], m7 = acc[7][ci];

                float l10 = sigf(i0 + m0);
                float l11 = fmaxf(i1 + m1, 0.0f);
                float l12 = sigf(i2 + m2);
                float l13 = fmaxf(i3 * m3, 0.0f);
                float l14 = tanhf_fast(i4 + m4);
                float l15 = sigf(i5 + m5);
                float l16 = tanhf_fast(i6 + m6);
                float l17 = sigf(i7 + m7);

                float l20 = tanhf_fast(l10 * l11);
                float l21 = tanhf_fast(l12 + l13);
                float l22 = tanhf_fast(l14 * l15);
                float l23 = sigf(l16 + l17);

                l20 = tanhf_fast(l20 + creg[ci]);
                float nc  = l20 * l21;
                float l31 = tanhf_fast(l22 + l23);
                float nh  = tanhf_fast(nc * l31);

                creg[ci] = nc;
                nh2[us]  = nh;
            }
            *reinterpret_cast<float2*>(&hout[(b0 + row) * U_ + u0 + uu0]) =
                make_float2(nh2[0], nh2[1]);
        }

        if (t != T_ - 1) group_barrier(tid, bx);
    }
}

extern "C" void kernel_launch(void* const* d_in, const int* in_sizes, int n_in,
                              void* d_out, int out_size) {
    const float* x    = nullptr;
    const float* kern = nullptr;
    const float* W    = nullptr;
    for (int i = 0; i < n_in; i++) {
        if (in_sizes[i] == B_ * U_)       x    = (const float*)d_in[i];
        else if (in_sizes[i] == 8 * U_)   kern = (const float*)d_in[i];
        else if (in_sizes[i] == U_ * NCW) W    = (const float*)d_in[i];
    }
    float* out = (float*)d_out;

    cudaFuncSetAttribute(nas_hmma, cudaFuncAttributeMaxDynamicSharedMemorySize,
                         SMEM_TOTAL);
    nas_hmma<<<NBLK, NTHREADS, SMEM_TOTAL>>>(out, W, kern, x);
}

// round 9
// speedup vs baseline: 4.9531x; 1.5266x over previous
#include <cuda_runtime.h>
#include <cstdint>

// Problem constants
#define B_    512
#define U_    256
#define T_    256
#define NCW   2048   // 8*U

// Decomposition: 16 batch-groups x 8 unit-blocks = 128 persistent CTAs.
// CTA = 32 batch rows x 32 units (GEMM: M=32, N=256, K=256).
#define NBLK     128
#define NTHREADS 256    // 8 warps; each warp: full M x 32 cols (4 n8-tiles)
#define BM       32
#define GRP      8      // CTAs per batch group

// fp16 tiles, row pitch 264 fp16 = 528 B (132 words; 132 % 32 == 4 -> ldmatrix
// rows hit distinct 16B bank-groups => conflict-free)
#define LDWRD 132
#define A_OFF 0
#define B_OFF 16896               // 32*528
#define SMEM_TOTAL 152064         // + 256*528

// h ping-pong buffers (c never leaves registers)
__device__ float g_hA[B_ * U_];
__device__ float g_hB[B_ * U_];
// per-group monotonic barrier counters (one 128B line each; replay-safe)
__device__ unsigned g_arrive[16 * 32];

// ---- helpers ---------------------------------------------------------------
__device__ __forceinline__ uint32_t smem_u32(const void* p) {
    uint32_t a;
    asm("{ .reg .u64 t; cvta.to.shared.u64 t, %1; cvt.u32.u64 %0, t; }"
        : "=r"(a) : "l"(p));
    return a;
}
// pack {hi_elem, lo_elem} -> f16x2 (lo = lower k index / lower address)
__device__ __forceinline__ uint32_t hfpack(float hi, float lo) {
    uint32_t r;
    asm("cvt.rn.f16x2.f32 %0, %1, %2;" : "=r"(r) : "f"(hi), "f"(lo));
    return r;
}
__device__ __forceinline__ float sigf(float v) {
    return __fdividef(1.0f, 1.0f + __expf(-v));
}
__device__ __forceinline__ float tanhf_fast(float v) {
    return fmaf(2.0f, sigf(2.0f * v), -1.0f);
}
__device__ __forceinline__ void ldsm4(uint32_t* r, uint32_t addr) {
    asm volatile("ldmatrix.sync.aligned.m8n8.x4.shared.b16 {%0,%1,%2,%3}, [%4];"
                 : "=r"(r[0]), "=r"(r[1]), "=r"(r[2]), "=r"(r[3]) : "r"(addr));
}
__device__ __forceinline__ void mma16816(float* c, const uint32_t* a,
                                         uint32_t b0, uint32_t b1) {
    asm volatile(
        "mma.sync.aligned.m16n8k16.row.col.f32.f16.f16.f32 "
        "{%0,%1,%2,%3},{%4,%5,%6,%7},{%8,%9},{%0,%1,%2,%3};"
        : "+f"(c[0]), "+f"(c[1]), "+f"(c[2]), "+f"(c[3])
        : "r"(a[0]), "r"(a[1]), "r"(a[2]), "r"(a[3]), "r"(b0), "r"(b1));
}

// ---- group barrier (8 CTAs of one batch group) ------------------------------
__device__ __forceinline__ void group_barrier(int tid, int grp) {
    __syncthreads();
    if (tid == 0) {
        __threadfence();
        unsigned* ctr = &g_arrive[grp * 32];
        unsigned ticket = atomicAdd(ctr, 1u);
        unsigned target = (ticket & ~(GRP - 1u)) + GRP;
        volatile unsigned* p = ctr;
        while ((int)(*p - target) < 0) { }
        __threadfence();
    }
    __syncthreads();
}

extern __shared__ char smem[];

__global__ __launch_bounds__(NTHREADS, 1)
void nas_hmma(float* __restrict__ out,
              const float* __restrict__ W,
              const float* __restrict__ kern,
              const float* __restrict__ x)
{
    uint32_t* Aw = reinterpret_cast<uint32_t*>(smem + A_OFF);  // [32][LDWRD]
    uint32_t* Bw = reinterpret_cast<uint32_t*>(smem + B_OFF);  // [256][LDWRD]

    const int tid  = threadIdx.x;
    const int wid  = tid >> 5;
    const int lane = tid & 31;
    const int quad = lane >> 2;     // 0..7
    const int ql   = lane & 3;      // 0..3
    const int bx   = blockIdx.x >> 3;   // batch group (32 rows), 0..15
    const int by   = blockIdx.x & 7;    // unit block (32 units), 0..7
    const int b0   = bx * BM;
    const int u0   = by * 32;

    const int uu   = wid * 4 + ql;      // thread's unit within CTA (0..31)

    // ---- Prologue: W slice -> fp16 B tile with gate-interleaved column
    // permutation. Logical col q = g*32 + u maps to physical row
    // P = (u>>2)*32 + (g>>1)*8 + (u&3)*2 + (g&1), so that warp w's 4 n8-tiles
    // give each thread all 8 gates of unit w*4+ql in its accumulators.
    for (int i = 0; i < 128; i++) {
        int p  = tid + i * NTHREADS;    // 32768 = 256 q x 128 k-pairs
        int q  = p & 255;
        int kp = p >> 8;
        int g  = q >> 5;
        int u  = q & 31;
        int gcol = g * U_ + u0 + u;
        float w0 = W[(size_t)(2 * kp) * NCW + gcol];
        float w1 = W[(size_t)(2 * kp + 1) * NCW + gcol];
        int P = ((u >> 2) << 5) + ((g >> 1) << 3) + ((u & 3) << 1) + (g & 1);
        Bw[P * LDWRD + kp] = hfpack(w1, w0);
    }
    // kernel weights for this thread's unit, all 8 gates
    float kr[8];
    #pragma unroll
    for (int g = 0; g < 8; g++)
        kr[g] = __ldg(&kern[g * U_ + u0 + uu]);

    // ldmatrix base addresses (byte offsets advance 32B per 16-k step)
    const uint32_t sA = smem_u32(smem) + A_OFF;
    const uint32_t sB = smem_u32(smem) + B_OFF;
    const int rowA  = ((lane >> 3) & 1) * 8 + (lane & 7);
    const uint32_t aBase0 = sA + rowA * 528 + (lane >> 4) * 16;
    const uint32_t aBase1 = aBase0 + 16 * 528;
    uint32_t bBase[2];
    #pragma unroll
    for (int cb = 0; cb < 2; cb++) {
        int tile = cb * 2 + (lane >> 4);
        int P    = wid * 32 + tile * 8 + (lane & 7);
        bBase[cb] = sB + P * 528 + ((lane >> 3) & 1) * 16;
    }

    float creg[4] = {0.0f, 0.0f, 0.0f, 0.0f};   // c for 4 rows x 1 unit
    __syncthreads();

    for (int t = 0; t < T_; t++) {
        const float* hin  = (t & 1) ? g_hB : g_hA;
        float*       hout = (t == T_ - 1) ? out : ((t & 1) ? g_hA : g_hB);

        float acc[2][4][4];                       // [m-tile][n-tile][frag]
        #pragma unroll
        for (int mt = 0; mt < 2; mt++)
            #pragma unroll
            for (int j = 0; j < 4; j++)
                #pragma unroll
                for (int v = 0; v < 4; v++)
                    acc[mt][j][v] = 0.0f;

        if (t > 0) {
            // ---- h -> fp16 A tile: 32 rows x 32 chunks(8 floats) -----------
            #pragma unroll
            for (int i = 0; i < 4; i++) {
                int idx = tid + i * NTHREADS;     // 0..1023
                int row = idx >> 5;
                int c8  = idx & 31;
                const float4* src = reinterpret_cast<const float4*>(
                    &hin[(b0 + row) * U_ + c8 * 8]);
                float4 v0 = __ldcg(src);
                float4 v1 = __ldcg(src + 1);
                uint32_t p0 = hfpack(v0.y, v0.x);
                uint32_t p1 = hfpack(v0.w, v0.z);
                uint32_t p2 = hfpack(v1.y, v1.x);
                uint32_t p3 = hfpack(v1.w, v1.z);
                *reinterpret_cast<uint4*>(&Aw[row * LDWRD + c8 * 4]) =
                    make_uint4(p0, p1, p2, p3);
            }
            __syncthreads();

            // ---- HMMA GEMM: M=32, N=256, K=256 (16 k-steps) ----------------
            #pragma unroll
            for (int ks = 0; ks < 16; ks++) {
                uint32_t a0[4], a1[4];
                ldsm4(a0, aBase0 + ks * 32);
                ldsm4(a1, aBase1 + ks * 32);
                #pragma unroll
                for (int cb = 0; cb < 2; cb++) {
                    uint32_t b[4];
                    ldsm4(b, bBase[cb] + ks * 32);
                    mma16816(acc[0][cb * 2 + 0], a0, b[0], b[1]);
                    mma16816(acc[0][cb * 2 + 1], a0, b[2], b[3]);
                    mma16816(acc[1][cb * 2 + 0], a1, b[0], b[1]);
                    mma16816(acc[1][cb * 2 + 1], a1, b[2], b[3]);
                }
            }
        }

        // ---- In-register NASCell epilogue: 4 rows x 1 unit per thread ------
        // acc[mt][j][rsel*2+gb] = m for row (mt*16 + rsel*8 + quad),
        // gate (2j+gb), unit uu.
        #pragma unroll
        for (int rr = 0; rr < 4; rr++) {
            const int mt   = rr >> 1;
            const int rsel = rr & 1;
            const int row  = mt * 16 + rsel * 8 + quad;
            float xv = __ldg(&x[(b0 + row) * U_ + t]);

            float i0 = xv * kr[0], m0 = acc[mt][0][rsel * 2 + 0];
            float i1 = xv * kr[1], m1 = acc[mt][0][rsel * 2 + 1];
            float i2 = xv * kr[2], m2 = acc[mt][1][rsel * 2 + 0];
            float i3 = xv * kr[3], m3 = acc[mt][1][rsel * 2 + 1];
            float i4 = xv * kr[4], m4 = acc[mt][2][rsel * 2 + 0];
            float i5 = xv * kr[5], m5 = acc[mt][2][rsel * 2 + 1];
            float i6 = xv * kr[6], m6 = acc[mt][3][rsel * 2 + 0];
            float i7 = xv * kr[7], m7 = acc[mt][3][rsel * 2 + 1];

            float l10 = sigf(i0 + m0);
            float l11 = fmaxf(i1 + m1, 0.0f);
            float l12 = sigf(i2 + m2);
            float l13 = fmaxf(i3 * m3, 0.0f);
            float l14 = tanhf_fast(i4 + m4);
            float l15 = sigf(i5 + m5);
            float l16 = tanhf_fast(i6 + m6);
            float l17 = sigf(i7 + m7);

            float l20 = tanhf_fast(l10 * l11);
            float l21 = tanhf_fast(l12 + l13);
            float l22 = tanhf_fast(l14 * l15);
            float l23 = sigf(l16 + l17);

            l20 = tanhf_fast(l20 + creg[rr]);
            float nc  = l20 * l21;
            float l31 = tanhf_fast(l22 + l23);
            float nh  = tanhf_fast(nc * l31);

            creg[rr] = nc;
            hout[(b0 + row) * U_ + u0 + uu] = nh;
        }

        if (t != T_ - 1) group_barrier(tid, bx);
    }
}

extern "C" void kernel_launch(void* const* d_in, const int* in_sizes, int n_in,
                              void* d_out, int out_size) {
    const float* x    = nullptr;
    const float* kern = nullptr;
    const float* W    = nullptr;
    for (int i = 0; i < n_in; i++) {
        if (in_sizes[i] == B_ * U_)       x    = (const float*)d_in[i];
        else if (in_sizes[i] == 8 * U_)   kern = (const float*)d_in[i];
        else if (in_sizes[i] == U_ * NCW) W    = (const float*)d_in[i];
    }
    float* out = (float*)d_out;

    cudaFuncSetAttribute(nas_hmma, cudaFuncAttributeMaxDynamicSharedMemorySize,
                         SMEM_TOTAL);
    nas_hmma<<<NBLK, NTHREADS, SMEM_TOTAL>>>(out, W, kern, x);
}